// round 8
// baseline (speedup 1.0000x reference)
#include <cuda_runtime.h>

// SCCT_NGT: 5000-step explicit PDE loop on NX=64 with tiny MLP closure,
// then phi2 = mean(u^2) and histogram entropy H of |u|/max.
//
// One persistent CTA, 256 threads = 8 warps (2/SMSP). Thread t: point
// p = t>>2, sub = t&3 owns an 8-unit slice of the 32 hidden units.
//
// R8:
//  - split store: after ONE shfl_xor(1) hop, lane sub=0 stores
//    base + DTg*s(units 0..15) into bufM, lane sub=2 stores DTg*s(16..31)
//    into bufP; consumers read M+P. Removes the second 26-cyc shfl hop.
//  - packed fma.rn.f32x2 (Blackwell FFMA2) for z and accumulate: halves
//    FMA-pipe pressure so it hides fully under the 128-cyc/SMSP MUFU floor.

#define NXc 64
#define HIDc 16
#define UPT 8   // hidden units per thread (4 f32x2 pairs)

typedef unsigned long long u64p;

__device__ __forceinline__ float tanhf_mufu(float x) {
    float y; asm("tanh.approx.f32 %0, %1;" : "=f"(y) : "f"(x)); return y;
}
__device__ __forceinline__ u64p pack2(float lo, float hi) {
    u64p r; asm("mov.b64 %0, {%1, %2};" : "=l"(r) : "f"(lo), "f"(hi)); return r;
}
__device__ __forceinline__ void unpack2(u64p v, float& lo, float& hi) {
    asm("mov.b64 {%0, %1}, %2;" : "=f"(lo), "=f"(hi) : "l"(v));
}
__device__ __forceinline__ u64p fma2(u64p a, u64p b, u64p c) {
    u64p r; asm("fma.rn.f32x2 %0, %1, %2, %3;" : "=l"(r) : "l"(a), "l"(b), "l"(c));
    return r;
}

__global__ __launch_bounds__(256, 1)
void scct_kernel(const float* __restrict__ u0,
                 const float* __restrict__ w1, const float* __restrict__ b1,
                 const float* __restrict__ w2, const float* __restrict__ b2,
                 const float* __restrict__ wc, const float* __restrict__ bc,
                 const float* __restrict__ gammap, const int* __restrict__ Ntp,
                 float* __restrict__ out)
{
    __shared__ float bufM[2][NXc + 2];   // main part (lane sub==0)
    __shared__ float bufP[2][NXc + 2];   // partial (lane sub==2); u = M + P
    __shared__ float s2red[NXc];
    __shared__ float vmred[NXc];
    __shared__ int   hist[NXc];

    const int t   = threadIdx.x;
    const int p   = t >> 2;      // grid point 0..63
    const int sub = t & 3;       // 4 threads per point
    const float bmask = (p == 0 || p == NXc - 1) ? 0.0f : 1.0f;  // Dirichlet

    const float gamma = gammap[0];
    const int   Nt    = Ntp[0];
    const float bcv   = bc[0];

    const float DTf  = (float)1e-4;
    const float R2DX = 31.5f;     // 1/(2*DX), exact
    const float RDX2 = 3969.0f;   // 1/DX^2, exact

    const float DTf_m  = DTf * bmask;
    const float DTg_m  = DTf * gamma * bmask;
    const float DTgb_m = DTf * gamma * bcv * bmask;
    const float K08R   = 0.8f * RDX2;        // core: (um+up) coeff
    const float C1     = 0.5f - 2.0f * K08R; // core: uc coeff

    // This thread's 8-unit weight slice, stencil pre-folded, packed in pairs:
    //   z_j = um*(RDX2*wq - R2DX*wb) + uc*(wa - 2*RDX2*wq)
    //       + up*(R2DX*wb + RDX2*wq) + bb
    const float* W  = (sub >> 1) ? w2 : w1;
    const float* Bp = (sub >> 1) ? b2 : b1;
    const int j0 = (sub & 1) * UPT;
    u64p AwP[UPT/2], BwP[UPT/2], CwP[UPT/2], bbP[UPT/2], cwP[UPT/2];
#pragma unroll
    for (int k = 0; k < UPT / 2; k++) {
        float A2[2], B2[2], C2[2], b2r[2], c2[2];
#pragma unroll
        for (int e = 0; e < 2; e++) {
            int j = j0 + 2 * k + e;
            float wa = W[j * 3 + 0];
            float wb = W[j * 3 + 1];
            float wq = W[j * 3 + 2];
            A2[e]  = RDX2 * wq - R2DX * wb;
            B2[e]  = wa - 2.0f * RDX2 * wq;
            C2[e]  = R2DX * wb + RDX2 * wq;
            b2r[e] = Bp[j];
            c2[e]  = wc[(sub >> 1) * HIDc + j];
        }
        AwP[k] = pack2(A2[0], A2[1]);
        BwP[k] = pack2(B2[0], B2[1]);
        CwP[k] = pack2(C2[0], C2[1]);
        bbP[k] = pack2(b2r[0], b2r[1]);
        cwP[k] = pack2(c2[0], c2[1]);
    }

    // Init shared buffers (ghosts zero everywhere; never rewritten).
    if (t < NXc + 2) {
        bufM[0][t] = 0.0f; bufM[1][t] = 0.0f;
        bufP[0][t] = 0.0f; bufP[1][t] = 0.0f;
    }
    __syncthreads();
    if (t < NXc) bufM[0][t + 1] = u0[t];
    __syncthreads();

    int cur = 0;
    for (int it = 0; it < Nt; ++it) {
        const float um = bufM[cur][p]     + bufP[cur][p];
        const float uc = bufM[cur][p + 1] + bufP[cur][p + 1];
        const float up = bufM[cur][p + 2] + bufP[cur][p + 2];

        // core path runs parallel to the tanh block (only lane 0 uses base)
        const float core = fmaf(um + up, K08R, fmaf(uc, C1, -(uc * uc * uc)));
        const float base = fmaf(DTf_m, core, uc * bmask) + DTgb_m;

        const u64p umP = pack2(um, um);
        const u64p ucP = pack2(uc, uc);
        const u64p upP = pack2(up, up);

        u64p acc0 = pack2(0.0f, 0.0f);
        u64p acc1 = acc0;
#pragma unroll
        for (int k = 0; k < UPT / 2; k += 2) {
            u64p za = fma2(upP, CwP[k],   fma2(ucP, BwP[k],   fma2(umP, AwP[k],   bbP[k])));
            u64p zb = fma2(upP, CwP[k+1], fma2(ucP, BwP[k+1], fma2(umP, AwP[k+1], bbP[k+1])));
            float z0, z1, z2, z3;
            unpack2(za, z0, z1);
            unpack2(zb, z2, z3);
            u64p ta = pack2(tanhf_mufu(z0), tanhf_mufu(z1));
            u64p tb = pack2(tanhf_mufu(z2), tanhf_mufu(z3));
            acc0 = fma2(cwP[k],   ta, acc0);
            acc1 = fma2(cwP[k+1], tb, acc1);
        }
        float a0, a1, a2, a3;
        unpack2(acc0, a0, a1);
        unpack2(acc1, a2, a3);
        float s = (a0 + a1) + (a2 + a3);

        // One hop: lane 0 gets units 0..15 sum, lane 2 gets units 16..31 sum.
        s += __shfl_xor_sync(0xffffffffu, s, 1);

        if ((sub & 1) == 0) {
            if (sub == 0) bufM[cur ^ 1][p + 1] = fmaf(DTg_m, s, base);
            else          bufP[cur ^ 1][p + 1] = DTg_m * s;
        }
        __syncthreads();
        cur ^= 1;
    }

    // ---- Final statistics ----
    if (t < NXc) {
        float v = bufM[cur][t + 1] + bufP[cur][t + 1];
        out[t]     = v;
        s2red[t]   = v * v;
        vmred[t]   = fabsf(v);
        hist[t]    = 0;
    }
    __syncthreads();

    if (t == 0) {
        float s2 = 0.0f, vmax = 0.0f;
        for (int i = 0; i < NXc; i++) {
            s2   += s2red[i];
            vmax  = fmaxf(vmax, vmred[i]);
        }
        out[NXc] = s2 * (1.0f / 64.0f);   // phi2 = mean(u^2)

        const float vden = fmaxf(vmax, 1e-12f);
        for (int i = 0; i < NXc; i++) {
            float vn = vmred[i] / vden;   // in [0, 1]
            int b = (int)floorf(vn * 64.0f);
            if (b > 63) b = 63;
            if (b < 0)  b = 0;
            // Exact searchsorted(edges, vn, 'right'): edges k/64 exact in fp32.
            while (b > 0  && vn <  (float)b       * (1.0f / 64.0f)) b--;
            while (b < 63 && vn >= (float)(b + 1) * (1.0f / 64.0f)) b++;
            hist[b]++;
        }
        float H = 0.0f;
        for (int i = 0; i < NXc; i++) {
            float pb = (float)hist[i] * (1.0f / 64.0f);
            H -= pb * logf(pb + 1e-12f);
        }
        if (vmax < 1e-12f) H = 0.0f;
        out[NXc + 1] = H;
    }
}

extern "C" void kernel_launch(void* const* d_in, const int* in_sizes, int n_in,
                              void* d_out, int out_size) {
    const float* u0    = (const float*)d_in[0];
    const float* w1    = (const float*)d_in[1];
    const float* b1    = (const float*)d_in[2];
    const float* w2    = (const float*)d_in[3];
    const float* b2    = (const float*)d_in[4];
    const float* wc    = (const float*)d_in[5];
    const float* bc    = (const float*)d_in[6];
    const float* gamma = (const float*)d_in[7];
    const int*   Nt    = (const int*)d_in[8];
    float* out = (float*)d_out;

    scct_kernel<<<1, 256>>>(u0, w1, b1, w2, b2, wc, bc, gamma, Nt, out);
}